// round 1
// baseline (speedup 1.0000x reference)
#include <cuda_runtime.h>
#include <math.h>

// LogSparseAttention, B=2, L=S=2048, H=8, E=D=64, fp32.
// Mask structure (win_len == sub_len == 2048, log_l = 11):
//   row i < 22           : keys 0..i (full causal)
//   row i >= 22          : keys i-10..i  plus  i-10-2^k (k=0..10, if >= 0)
// => at most 22 keys per query row. One warp per (b,l,h) query row.

#define FULL_MASK 0xffffffffu

__global__ __launch_bounds__(256, 8)
void logsparse_attn_kernel(const float* __restrict__ Q,
                           const float* __restrict__ K,
                           const float* __restrict__ V,
                           float* __restrict__ O)
{
    constexpr int H = 8;
    constexpr int L = 2048;
    constexpr int E = 64;
    const float scale = 0.125f;  // 1/sqrt(64)

    const int warp = (blockIdx.x * blockDim.x + threadIdx.x) >> 5;
    const int lane = threadIdx.x & 31;

    // h fastest: 8 warps of a block share (b,l) -> contiguous K/V segments.
    const int h = warp % H;
    const int l = (warp / H) % L;
    const int b = warp / (H * L);

    // Load my 2 elements of q (E = 64 = 2 * 32).
    const size_t rowbase = ((size_t)((b * L + l) * H + h)) * E;
    const float q0 = Q[rowbase + lane];
    const float q1 = Q[rowbase + lane + 32];

    // Per-lane key index for this row's sparse pattern.
    int key;
    bool valid;
    if (l < 22) {                     // (win//sub)*2*log_l = 22 > i  -> causal
        key = lane;
        valid = (lane <= l);
    } else {
        if (lane < 11) {              // band l-10..l
            key = l - lane;
            valid = true;
        } else if (lane < 22) {       // log taps l-10-2^(lane-11)
            key = l - 10 - (1 << (lane - 11));
            valid = (key >= 0);
        } else {
            key = 0;
            valid = false;
        }
    }
    const unsigned vmask = __ballot_sync(FULL_MASK, valid);

    // ---- Scores: cooperative dot per valid key (coalesced K loads) ----
    float myscore = -INFINITY;
    unsigned m = vmask;
    while (m) {
        const int j = __ffs(m) - 1;
        m &= m - 1;
        const int kj = __shfl_sync(FULL_MASK, key, j);
        const size_t kbase = ((size_t)((b * L + kj) * H + h)) * E;
        float p = fmaf(q0, K[kbase + lane], q1 * K[kbase + lane + 32]);
        #pragma unroll
        for (int off = 16; off; off >>= 1)
            p += __shfl_xor_sync(FULL_MASK, p, off);
        if (lane == j) myscore = p * scale;
    }

    // ---- Softmax over valid lanes (masked lanes contribute exactly 0) ----
    float s = valid ? myscore : -INFINITY;
    float mx = s;
    #pragma unroll
    for (int off = 16; off; off >>= 1)
        mx = fmaxf(mx, __shfl_xor_sync(FULL_MASK, mx, off));
    float p = valid ? __expf(s - mx) : 0.0f;
    float sum = p;
    #pragma unroll
    for (int off = 16; off; off >>= 1)
        sum += __shfl_xor_sync(FULL_MASK, sum, off);
    const float w = p / sum;

    // ---- Weighted V accumulation (coalesced V loads) ----
    float a0 = 0.0f, a1 = 0.0f;
    m = vmask;
    while (m) {
        const int j = __ffs(m) - 1;
        m &= m - 1;
        const float wj = __shfl_sync(FULL_MASK, w, j);
        const int kj = __shfl_sync(FULL_MASK, key, j);
        const size_t vbase = ((size_t)((b * L + kj) * H + h)) * E;
        a0 = fmaf(wj, V[vbase + lane], a0);
        a1 = fmaf(wj, V[vbase + lane + 32], a1);
    }

    O[rowbase + lane] = a0;
    O[rowbase + lane + 32] = a1;
}

extern "C" void kernel_launch(void* const* d_in, const int* in_sizes, int n_in,
                              void* d_out, int out_size)
{
    (void)in_sizes; (void)n_in; (void)out_size;
    const float* Q = (const float*)d_in[0];
    const float* K = (const float*)d_in[1];
    const float* V = (const float*)d_in[2];
    float* O = (float*)d_out;

    // B*H*L = 2*8*2048 = 32768 warps; 8 warps/block -> 4096 blocks.
    const int total_warps = 2 * 8 * 2048;
    const int threads = 256;
    const int blocks = total_warps / (threads / 32);
    logsparse_attn_kernel<<<blocks, threads>>>(Q, K, V, O);
}

// round 2
// speedup vs baseline: 1.9133x; 1.9133x over previous
#include <cuda_runtime.h>
#include <math.h>

// LogSparseAttention, B=2, L=S=2048, H=8, E=D=64, fp32.
// Row l attends to <=22 keys: band l-10..l plus log taps l-10-2^k (l>=22),
// or full causal 0..l (l<22). One warp per (b,l,h) row.
//
// Pair-split layout: lanes 0-15 <-> even slot of each pair (dims 4i..4i+3),
// lanes 16-31 <-> odd slot. One LDG.128 serves two keys.

#define FULL_MASK 0xffffffffu
#define NPAIR 12   // 24 slots

__global__ __launch_bounds__(256)
void logsparse_attn_kernel(const float* __restrict__ Q,
                           const float* __restrict__ K,
                           const float* __restrict__ V,
                           float* __restrict__ O)
{
    constexpr int H = 8;
    constexpr int L = 2048;
    const float scale = 0.125f;  // 1/sqrt(64)

    const int warp = (blockIdx.x * blockDim.x + threadIdx.x) >> 5;
    const int lane = threadIdx.x & 31;
    const int half = lane >> 4;          // 0: even slot, 1: odd slot
    const int li   = lane & 15;
    const int dimoff = li << 2;          // float4 chunk of E

    const int h = warp % H;
    const int l = (warp / H) % L;
    const int b = warp / (H * L);

    const int rowbase = ((b * L + l) * H + h) << 6;   // *64

    // q chunk for my 4 dims (upper half duplicates lower half's addresses)
    float4 q4 = *(const float4*)(Q + rowbase + dimoff);
    q4.x *= scale; q4.y *= scale; q4.z *= scale; q4.w *= scale;

    // ---- Per-pair key offsets (element offsets into K/V), reused twice ----
    const int cbase = (b << 20) + (h << 6) + dimoff;  // b*L*H*64 + h*64 + dim
    int koff[NPAIR];
    const bool smallrow = (l < 22);
    #pragma unroll
    for (int p = 0; p < NPAIR; ++p) {
        const int tt = 2 * p + half;          // my slot
        const int sh = (tt - 11) & 31;
        const int klog = l - 10 - (1 << sh);  // garbage if tt<11 (unused)
        int k  = (tt < 11) ? (l - tt) : klog;
        int kv = (tt < 11) ? 1 : (klog >= 0);
        if (smallrow) { k = tt; kv = (tt <= l); }
        const int kc = kv ? k : 0;
        koff[p] = cbase + (kc << 9);          // kc * H*64
    }

    // ---- Scores: one LDG.128 + 4-level half-butterfly per 2 keys ----
    float myscore = -INFINITY;
    #pragma unroll
    for (int p = 0; p < NPAIR; ++p) {
        const float4 k4 = *(const float4*)(K + koff[p]);
        float pp = q4.x * k4.x;
        pp = fmaf(q4.y, k4.y, pp);
        pp = fmaf(q4.z, k4.z, pp);
        pp = fmaf(q4.w, k4.w, pp);
        pp += __shfl_xor_sync(FULL_MASK, pp, 8);
        pp += __shfl_xor_sync(FULL_MASK, pp, 4);
        pp += __shfl_xor_sync(FULL_MASK, pp, 2);
        pp += __shfl_xor_sync(FULL_MASK, pp, 1);
        // slot 2p score in lanes 0-15, slot 2p+1 in lanes 16-31.
        const float sb = __shfl_sync(FULL_MASK, pp, (lane & 1) << 4);
        if ((lane >> 1) == p) myscore = sb;   // lane j holds score of slot j
    }

    // ---- Validity of MY lane's slot (lane == slot index) ----
    bool v;
    if (smallrow) {
        v = (lane <= l);
    } else {
        const int klog = l - 10 - (1 << ((lane - 11) & 31));
        v = (lane < 11) | ((lane < 22) & (klog >= 0));
    }

    // ---- Softmax over slots ----
    float s = v ? myscore : -INFINITY;
    float mx = s;
    #pragma unroll
    for (int off = 16; off; off >>= 1)
        mx = fmaxf(mx, __shfl_xor_sync(FULL_MASK, mx, off));
    float pe = v ? __expf(s - mx) : 0.0f;
    float sum = pe;
    #pragma unroll
    for (int off = 16; off; off >>= 1)
        sum += __shfl_xor_sync(FULL_MASK, sum, off);
    const float w = pe / sum;

    // ---- V accumulation: halves take even/odd keys ----
    float4 accA = make_float4(0.f, 0.f, 0.f, 0.f);
    float4 accB = make_float4(0.f, 0.f, 0.f, 0.f);
    #pragma unroll
    for (int p = 0; p < NPAIR; ++p) {
        const float wj = __shfl_sync(FULL_MASK, w, 2 * p + half);
        const float4 v4 = *(const float4*)(V + koff[p]);
        if (p & 1) {
            accB.x = fmaf(wj, v4.x, accB.x);
            accB.y = fmaf(wj, v4.y, accB.y);
            accB.z = fmaf(wj, v4.z, accB.z);
            accB.w = fmaf(wj, v4.w, accB.w);
        } else {
            accA.x = fmaf(wj, v4.x, accA.x);
            accA.y = fmaf(wj, v4.y, accA.y);
            accA.z = fmaf(wj, v4.z, accA.z);
            accA.w = fmaf(wj, v4.w, accA.w);
        }
    }
    float4 acc;
    acc.x = accA.x + accB.x;
    acc.y = accA.y + accB.y;
    acc.z = accA.z + accB.z;
    acc.w = accA.w + accB.w;

    // combine even-key half with odd-key half
    acc.x += __shfl_xor_sync(FULL_MASK, acc.x, 16);
    acc.y += __shfl_xor_sync(FULL_MASK, acc.y, 16);
    acc.z += __shfl_xor_sync(FULL_MASK, acc.z, 16);
    acc.w += __shfl_xor_sync(FULL_MASK, acc.w, 16);

    if (lane < 16)
        *(float4*)(O + rowbase + dimoff) = acc;
}

extern "C" void kernel_launch(void* const* d_in, const int* in_sizes, int n_in,
                              void* d_out, int out_size)
{
    (void)in_sizes; (void)n_in; (void)out_size;
    const float* Q = (const float*)d_in[0];
    const float* K = (const float*)d_in[1];
    const float* V = (const float*)d_in[2];
    float* O = (float*)d_out;

    const int total_warps = 2 * 8 * 2048;     // B*H*L
    const int threads = 256;
    const int blocks = total_warps / (threads / 32);
    logsparse_attn_kernel<<<blocks, threads>>>(Q, K, V, O);
}